// round 11
// baseline (speedup 1.0000x reference)
#include <cuda_runtime.h>
#include <cuda_bf16.h>
#include <cstdint>

#define BB 8
#define NN 256
#define MM 16
#define DD 256

// scratch: bf16 centroids, bf16 embeddings, fp32 row sq_norms
__device__ __align__(16) __nv_bfloat16 g_C[BB * NN * DD];
__device__ __align__(16) __nv_bfloat16 g_Ebf[BB * NN * MM * DD];
__device__ float g_SQN[BB * NN * MM];

// ============================ helpers ============================
__device__ __forceinline__ uint32_t smem_u32(const void* p) {
    uint32_t a;
    asm("{ .reg .u64 t; cvta.to.shared.u64 t, %1; cvt.u32.u64 %0, t; }"
        : "=r"(a) : "l"(p));
    return a;
}
__device__ __forceinline__ float ex2f(float x) {
    float y; asm("ex2.approx.ftz.f32 %0, %1;" : "=f"(y) : "f"(x)); return y;
}
__device__ __forceinline__ float lg2f(float x) {
    float y; asm("lg2.approx.ftz.f32 %0, %1;" : "=f"(y) : "f"(x)); return y;
}
__device__ __forceinline__ void ldm_x4(uint32_t* r, uint32_t addr) {
    asm volatile("ldmatrix.sync.aligned.m8n8.x4.shared.b16 {%0,%1,%2,%3}, [%4];"
                 : "=r"(r[0]), "=r"(r[1]), "=r"(r[2]), "=r"(r[3])
                 : "r"(addr));
}
__device__ __forceinline__ void mma16816(float* d, const uint32_t* a,
                                         uint32_t b0, uint32_t b1) {
    asm volatile(
        "mma.sync.aligned.m16n8k16.row.col.f32.bf16.bf16.f32 "
        "{%0,%1,%2,%3}, {%4,%5,%6,%7}, {%8,%9}, {%0,%1,%2,%3};"
        : "+f"(d[0]), "+f"(d[1]), "+f"(d[2]), "+f"(d[3])
        : "r"(a[0]), "r"(a[1]), "r"(a[2]), "r"(a[3]), "r"(b0), "r"(b1));
}
__device__ __forceinline__ void cp_async16(uint32_t dst, const void* src) {
    asm volatile("cp.async.cg.shared.global [%0], [%1], 16;"
                 :: "r"(dst), "l"(src) : "memory");
}

// ============================ Kernel 1: centroids + bf16 E + sq_norms ============================
__global__ void centroid_kernel(const float* __restrict__ E, float* __restrict__ out) {
    __shared__ float ssq[4][16][68];
    int tid = threadIdx.x;
    int idx = blockIdx.x * 256 + tid;
    if (idx == 0) out[0] = 0.f;
    int d4 = idx & 63, bn = idx >> 6;
    int g  = tid >> 6;
    const float4* p = (const float4*)E + (size_t)bn * MM * 64 + d4;
    float4 s = make_float4(0.f, 0.f, 0.f, 0.f);
#pragma unroll
    for (int m = 0; m < MM; m++) {
        float4 v = p[m * 64];
        s.x += v.x; s.y += v.y; s.z += v.z; s.w += v.w;
        ssq[g][m][d4] = v.x*v.x + v.y*v.y + v.z*v.z + v.w*v.w;
        __nv_bfloat162 lo = __floats2bfloat162_rn(v.x, v.y);
        __nv_bfloat162 hi = __floats2bfloat162_rn(v.z, v.w);
        uint2 pk; pk.x = *(uint32_t*)&lo; pk.y = *(uint32_t*)&hi;
        *(uint2*)(g_Ebf + ((size_t)bn * MM + m) * DD + d4 * 4) = pk;
    }
    const float inv = 1.0f / MM;
    __nv_bfloat162 lo = __floats2bfloat162_rn(s.x * inv, s.y * inv);
    __nv_bfloat162 hi = __floats2bfloat162_rn(s.z * inv, s.w * inv);
    uint2 pk; pk.x = *(uint32_t*)&lo; pk.y = *(uint32_t*)&hi;
    *(uint2*)(g_C + (size_t)bn * DD + d4 * 4) = pk;

    __syncthreads();
    int lr = tid >> 2, q = tid & 3;
    float acc = 0.f;
#pragma unroll
    for (int k = 0; k < 16; k++) acc += ssq[lr >> 4][lr & 15][q * 16 + k];
    acc += __shfl_xor_sync(0xFFFFFFFFu, acc, 1);
    acc += __shfl_xor_sync(0xFFFFFFFFu, acc, 2);
    if (q == 0) g_SQN[blockIdx.x * 64 + lr] = acc;
}

// ============================ Kernel 2: K-split pipelined GEMM + fused LSE ==================
// Grid 128, 512 thr. CTA: 2 tiles of 128 rows x 256 cols. A/B staged in two K-halves.
// smem: misc 8KB | Ak0 32KB | Ak1 32KB | Bk0 64KB | Bk1 64KB
static constexpr int SQN0_OFF = 0;        // 128 floats
static constexpr int SQN1_OFF = 512;      // 128 floats
static constexpr int MSB_OFF  = 1024;     // float2[128][4] = 4096 B
static constexpr int SELF_OFF = 5120;     // 128 floats
static constexpr int RED_OFF  = 5632;     // 4 floats
static constexpr int A_OFF    = 8192;     // 2 halves x 32768 (128 rows x 256B)
static constexpr int B_OFF    = 73728;    // 2 halves x 65536 (256 rows x 256B)
static constexpr int SMEM_TOTAL = 204800;

// 256B-row swizzle: un in [0,16), XOR low3 within 8-row blocks (conflict-free ldmatrix)
#define SWZ256(row, un) ((uint32_t)(row) * 256u + ((((uint32_t)(un)) ^ ((uint32_t)(row) & 7u)) << 4))

__global__ void __launch_bounds__(512, 1) loss_kernel(
    const float* __restrict__ wp,
    const float* __restrict__ bp,
    float* __restrict__ out)
{
    extern __shared__ char smem[];
    uint32_t sb = smem_u32(smem);
    int tid = threadIdx.x, wid = tid >> 5, L = tid & 31;
    int warpM = wid & 3, warpN = wid >> 2;   // 4x4 warp grid: warp tile 32 rows x 64 cols

    int bx    = blockIdx.x;        // 128 CTAs
    int batch = bx >> 4;
    int rtb   = (bx & 15) * 2;     // first of two 128-row tiles

    float w_s = *wp;
    float b_s = *bp;
    float*  sqn0 = (float*)(smem + SQN0_OFF);
    float*  sqn1 = (float*)(smem + SQN1_OFF);
    float2* msb  = (float2*)(smem + MSB_OFF);
    float*  SELF = (float*)(smem + SELF_OFF);
    float*  red  = (float*)(smem + RED_OFF);

    const char* Cg = (const char*)(g_C + (size_t)batch * NN * DD);
    const char* Ag0 = (const char*)(g_Ebf + ((size_t)(batch * 4096 + rtb * 128)) * DD);

    // ---- prologue: [Bk0 + Ak0(t0)] group, then [Bk1 + Ak1(t0)] group ----
#pragma unroll
    for (int h = 0; h < 2; h++) {
        // B K-half h: 4096 units (256 rows x 16)
#pragma unroll
        for (int it = 0; it < 8; it++) {
            int u = it * 512 + tid;
            int row = u >> 4, un = u & 15;
            cp_async16(sb + B_OFF + (uint32_t)h * 65536u + SWZ256(row, un),
                       Cg + (size_t)row * 512 + h * 256 + un * 16);
        }
        // A K-half h of tile 0: 2048 units (128 rows x 16)
#pragma unroll
        for (int it = 0; it < 4; it++) {
            int u = it * 512 + tid;
            int row = u >> 4, un = u & 15;
            cp_async16(sb + A_OFF + (uint32_t)h * 32768u + SWZ256(row, un),
                       Ag0 + (size_t)row * 512 + h * 256 + un * 16);
        }
        asm volatile("cp.async.commit_group;" ::: "memory");
    }
    if (tid < 128) {
        int base = batch * 4096 + rtb * 128;
        sqn0[tid] = g_SQN[base + tid];
        sqn1[tid] = g_SQN[base + 128 + tid];
    }

    // ---- invariant per-lane ldmatrix addressing (256B rows) ----
    uint32_t arsk = (uint32_t)((L >> 4) ^ (L & 7));
    uint32_t aB0  = sb + A_OFF + (uint32_t)(warpM * 32 + (L & 15)) * 256u;
    uint32_t aB1  = aB0 + 16 * 256;
    uint32_t brsk = (uint32_t)(((L >> 3) & 1) ^ (L & 7));
    uint32_t bB[4];
#pragma unroll
    for (int nb = 0; nb < 4; nb++)
        bB[nb] = sb + B_OFF +
                 (uint32_t)(warpN * 64 + nb * 16 + ((L >> 4) << 3) + (L & 7)) * 256u;

    const float L2E = 1.44269504f, LN2 = 0.69314718f;
    float wdiv = w_s * (1.0f / 15.0f);

    asm volatile("cp.async.wait_group 1;" ::: "memory");   // K-half 0 ready
    __syncthreads();

    for (int t2 = 0; t2 < 2; t2++) {
        int rt = rtb + t2;
        float* sqn = t2 ? sqn1 : sqn0;

        float acc[2][8][4];
#pragma unroll
        for (int f = 0; f < 2; f++)
#pragma unroll
            for (int j = 0; j < 8; j++)
#pragma unroll
                for (int u = 0; u < 4; u++) acc[f][j][u] = 0.f;

        // ---- mainloop over two K-halves, 8 ksteps each ----
#pragma unroll
        for (int h = 0; h < 2; h++) {
            uint32_t ah = (uint32_t)h * 32768u;
            uint32_t bh = (uint32_t)h * 65536u;
#pragma unroll
            for (int kk = 0; kk < 8; kk++) {
                uint32_t ku = (uint32_t)(kk * 2);
                uint32_t xa = ((ku ^ arsk) << 4);
                uint32_t xb = ((ku ^ brsk) << 4);
                uint32_t a0[4], a1[4];
                ldm_x4(a0, aB0 + ah + xa);
                ldm_x4(a1, aB1 + ah + xa);
#pragma unroll
                for (int nb = 0; nb < 4; nb++) {
                    uint32_t bf[4];
                    ldm_x4(bf, bB[nb] + bh + xb);
                    mma16816(acc[0][2 * nb],     a0, bf[0], bf[1]);
                    mma16816(acc[0][2 * nb + 1], a0, bf[2], bf[3]);
                    mma16816(acc[1][2 * nb],     a1, bf[0], bf[1]);
                    mma16816(acc[1][2 * nb + 1], a1, bf[2], bf[3]);
                }
            }
            if (h == 0 && t2 == 0) {
                asm volatile("cp.async.wait_group 0;" ::: "memory");  // K-half 1 ready
                __syncthreads();
            }
        }
        __syncthreads();   // all warps done reading A halves

        // prefetch tile-1 A (both K-halves) under the epilogue
        if (t2 == 0) {
            const char* Ag1 = Ag0 + (size_t)128 * 512;
#pragma unroll
            for (int h = 0; h < 2; h++) {
#pragma unroll
                for (int it = 0; it < 4; it++) {
                    int u = it * 512 + tid;
                    int row = u >> 4, un = u & 15;
                    cp_async16(sb + A_OFF + (uint32_t)h * 32768u + SWZ256(row, un),
                               Ag1 + (size_t)row * 512 + h * 256 + un * 16);
                }
            }
            asm volatile("cp.async.commit_group;" ::: "memory");
        }

        // ---- epilogue: in-place xv, per-warp partial LSE over its 64 cols ----
#pragma unroll
        for (int f = 0; f < 2; f++) {
            int dk  = rt * 8 + warpM * 2 + f;
            bool own = ((dk >> 6) == warpN);
#pragma unroll
            for (int rh = 0; rh < 2; rh++) {
                int row = warpM * 32 + f * 16 + rh * 8 + (L >> 2);
                float sq = sqn[row];
                float m = -1e30f, sself = 0.f;
#pragma unroll
                for (int j = 0; j < 8; j++) {
#pragma unroll
                    for (int cq = 0; cq < 2; cq++) {
                        float v = acc[f][j][rh * 2 + cq];
                        int col = warpN * 64 + (j >> 1) * 16 + (j & 1) * 8 + (L & 3) * 2 + cq;
                        bool dg = (col == dk);
                        float xv = dg ? fmaf(wdiv, fmaf(16.f, v, -sq), b_s)
                                      : fmaf(w_s, v, b_s);
                        if (dg) sself = xv;
                        acc[f][j][rh * 2 + cq] = xv;     // in-place: sum pass reads regs
                        m = fmaxf(m, xv);
                    }
                }
                m = fmaxf(m, __shfl_xor_sync(0xFFFFFFFFu, m, 1));
                m = fmaxf(m, __shfl_xor_sync(0xFFFFFFFFu, m, 2));
                float s = 0.f;
#pragma unroll
                for (int j = 0; j < 8; j++) {
#pragma unroll
                    for (int cq = 0; cq < 2; cq++)
                        s += ex2f((acc[f][j][rh * 2 + cq] - m) * L2E);
                }
                s += __shfl_xor_sync(0xFFFFFFFFu, s, 1);
                s += __shfl_xor_sync(0xFFFFFFFFu, s, 2);
                sself += __shfl_xor_sync(0xFFFFFFFFu, sself, 1);
                sself += __shfl_xor_sync(0xFFFFFFFFu, sself, 2);
                if ((L & 3) == 0) {
                    msb[row * 4 + warpN] = make_float2(m, s);
                    if (own) SELF[row] = sself;
                }
            }
        }
        __syncthreads();

        // ---- merge 4 warpN partials per row, reduce ----
        if (tid < 128) {
            float2 p0 = msb[tid * 4 + 0], p1 = msb[tid * 4 + 1];
            float2 p2 = msb[tid * 4 + 2], p3 = msb[tid * 4 + 3];
            float m = fmaxf(fmaxf(p0.x, p1.x), fmaxf(p2.x, p3.x));
            float s = p0.y * ex2f((p0.x - m) * L2E) + p1.y * ex2f((p1.x - m) * L2E)
                    + p2.y * ex2f((p2.x - m) * L2E) + p3.y * ex2f((p3.x - m) * L2E);
            float contrib = m + lg2f(s) * LN2 - SELF[tid];
            contrib += __shfl_xor_sync(0xFFFFFFFFu, contrib, 16);
            contrib += __shfl_xor_sync(0xFFFFFFFFu, contrib, 8);
            contrib += __shfl_xor_sync(0xFFFFFFFFu, contrib, 4);
            contrib += __shfl_xor_sync(0xFFFFFFFFu, contrib, 2);
            contrib += __shfl_xor_sync(0xFFFFFFFFu, contrib, 1);
            if (L == 0) {
                if (t2 == 0) red[wid] = contrib;
                else         red[wid] += contrib;
            }
        }
        if (t2 == 0) { asm volatile("cp.async.wait_group 0;" ::: "memory"); }
        __syncthreads();
    }

    if (tid == 0) atomicAdd(out, red[0] + red[1] + red[2] + red[3]);
}

// ============================ launch ============================
extern "C" void kernel_launch(void* const* d_in, const int* in_sizes, int n_in,
                              void* d_out, int out_size) {
    const float* E  = (const float*)d_in[0];
    const float* wp = (const float*)d_in[1];
    const float* bp = (const float*)d_in[2];
    float* out = (float*)d_out;

    centroid_kernel<<<BB * NN / 4, 256>>>(E, out);

    cudaFuncSetAttribute(loss_kernel, cudaFuncAttributeMaxDynamicSharedMemorySize, SMEM_TOTAL);
    loss_kernel<<<128, 512, SMEM_TOTAL>>>(wp, bp, out);
}

// round 12
// speedup vs baseline: 1.4815x; 1.4815x over previous
#include <cuda_runtime.h>
#include <cuda_bf16.h>
#include <cstdint>

#define BB 8
#define NN 256
#define MM 16
#define DD 256

// scratch: bf16 centroids, bf16 embeddings, fp32 row sq_norms
__device__ __align__(16) __nv_bfloat16 g_C[BB * NN * DD];
__device__ __align__(16) __nv_bfloat16 g_Ebf[BB * NN * MM * DD];
__device__ float g_SQN[BB * NN * MM];

// ============================ helpers ============================
__device__ __forceinline__ uint32_t smem_u32(const void* p) {
    uint32_t a;
    asm("{ .reg .u64 t; cvta.to.shared.u64 t, %1; cvt.u32.u64 %0, t; }"
        : "=r"(a) : "l"(p));
    return a;
}
__device__ __forceinline__ float ex2f(float x) {
    float y; asm("ex2.approx.ftz.f32 %0, %1;" : "=f"(y) : "f"(x)); return y;
}
__device__ __forceinline__ float lg2f(float x) {
    float y; asm("lg2.approx.ftz.f32 %0, %1;" : "=f"(y) : "f"(x)); return y;
}
__device__ __forceinline__ void ldm_x4(uint32_t* r, uint32_t addr) {
    asm volatile("ldmatrix.sync.aligned.m8n8.x4.shared.b16 {%0,%1,%2,%3}, [%4];"
                 : "=r"(r[0]), "=r"(r[1]), "=r"(r[2]), "=r"(r[3])
                 : "r"(addr));
}
__device__ __forceinline__ void mma16816(float* d, const uint32_t* a,
                                         uint32_t b0, uint32_t b1) {
    asm volatile(
        "mma.sync.aligned.m16n8k16.row.col.f32.bf16.bf16.f32 "
        "{%0,%1,%2,%3}, {%4,%5,%6,%7}, {%8,%9}, {%0,%1,%2,%3};"
        : "+f"(d[0]), "+f"(d[1]), "+f"(d[2]), "+f"(d[3])
        : "r"(a[0]), "r"(a[1]), "r"(a[2]), "r"(a[3]), "r"(b0), "r"(b1));
}
__device__ __forceinline__ void cp_async16(uint32_t dst, const void* src) {
    asm volatile("cp.async.cg.shared.global [%0], [%1], 16;"
                 :: "r"(dst), "l"(src) : "memory");
}

// ============================ Kernel 1: centroids + bf16 E + sq_norms ============================
__global__ void centroid_kernel(const float* __restrict__ E, float* __restrict__ out) {
    __shared__ float ssq[4][16][68];
    int tid = threadIdx.x;
    int idx = blockIdx.x * 256 + tid;
    if (idx == 0) out[0] = 0.f;
    int d4 = idx & 63, bn = idx >> 6;
    int g  = tid >> 6;
    const float4* p = (const float4*)E + (size_t)bn * MM * 64 + d4;
    float4 s = make_float4(0.f, 0.f, 0.f, 0.f);
#pragma unroll
    for (int m = 0; m < MM; m++) {
        float4 v = p[m * 64];
        s.x += v.x; s.y += v.y; s.z += v.z; s.w += v.w;
        ssq[g][m][d4] = v.x*v.x + v.y*v.y + v.z*v.z + v.w*v.w;
        __nv_bfloat162 lo = __floats2bfloat162_rn(v.x, v.y);
        __nv_bfloat162 hi = __floats2bfloat162_rn(v.z, v.w);
        uint2 pk; pk.x = *(uint32_t*)&lo; pk.y = *(uint32_t*)&hi;
        *(uint2*)(g_Ebf + ((size_t)bn * MM + m) * DD + d4 * 4) = pk;
    }
    const float inv = 1.0f / MM;
    __nv_bfloat162 lo = __floats2bfloat162_rn(s.x * inv, s.y * inv);
    __nv_bfloat162 hi = __floats2bfloat162_rn(s.z * inv, s.w * inv);
    uint2 pk; pk.x = *(uint32_t*)&lo; pk.y = *(uint32_t*)&hi;
    *(uint2*)(g_C + (size_t)bn * DD + d4 * 4) = pk;

    __syncthreads();
    int lr = tid >> 2, q = tid & 3;
    float acc = 0.f;
#pragma unroll
    for (int k = 0; k < 16; k++) acc += ssq[lr >> 4][lr & 15][q * 16 + k];
    acc += __shfl_xor_sync(0xFFFFFFFFu, acc, 1);
    acc += __shfl_xor_sync(0xFFFFFFFFu, acc, 2);
    if (q == 0) g_SQN[blockIdx.x * 64 + lr] = acc;
}

// ============================ Kernel 2: persistent GEMM + fused LSE (R8 base) ==================
static constexpr int SQN0_OFF = 0;        // 128 floats
static constexpr int SQN1_OFF = 512;      // 128 floats
static constexpr int MSB_OFF  = 1024;     // float2[128][4] = 4096 B
static constexpr int SELF_OFF = 5120;     // 128 floats
static constexpr int RED_OFF  = 5632;     // 4 floats
static constexpr int A_OFF    = 8192;     // 128 rows x 512 B = 65536
static constexpr int B_OFF    = 73728;    // 256 rows x 512 B = 131072
static constexpr int SMEM_TOTAL = 204800;

#define SWZ(row, un) ((uint32_t)(row) * 512u + ((((uint32_t)(un)) ^ ((uint32_t)(row) & 7u)) << 4))

__global__ void __launch_bounds__(512, 1) loss_kernel(
    const float* __restrict__ wp,
    const float* __restrict__ bp,
    float* __restrict__ out)
{
    extern __shared__ char smem[];
    uint32_t sb = smem_u32(smem);
    int tid = threadIdx.x, wid = tid >> 5, L = tid & 31;
    int warpM = wid & 3, warpN = wid >> 2;   // 4x4 warp grid: warp tile 32 rows x 64 cols

    int bx    = blockIdx.x;        // 128 CTAs
    int batch = bx >> 4;
    int rtb   = (bx & 15) * 2;     // first of two 128-row tiles

    float w_s = *wp;
    float b_s = *bp;
    float*  sqn0 = (float*)(smem + SQN0_OFF);
    float*  sqn1 = (float*)(smem + SQN1_OFF);
    float2* msb  = (float2*)(smem + MSB_OFF);
    float*  SELF = (float*)(smem + SELF_OFF);
    float*  red  = (float*)(smem + RED_OFF);

    // ---- prologue: B tile (128 KB) + A tile 0 (64 KB) via cp.async; both sqn tiles ----
    {
        const char* Cg = (const char*)(g_C + (size_t)batch * NN * DD);
#pragma unroll
        for (int it = 0; it < 16; it++) {
            int u = it * 512 + tid;
            cp_async16(sb + B_OFF + SWZ(u >> 5, u & 31), Cg + (size_t)u * 16);
        }
        const char* Ag = (const char*)(g_Ebf + ((size_t)(batch * 4096 + rtb * 128)) * DD);
#pragma unroll
        for (int it = 0; it < 8; it++) {
            int u = it * 512 + tid;
            cp_async16(sb + A_OFF + SWZ(u >> 5, u & 31), Ag + (size_t)u * 16);
        }
        asm volatile("cp.async.commit_group;" ::: "memory");
        if (tid < 128) {
            int base = batch * 4096 + rtb * 128;
            sqn0[tid] = g_SQN[base + tid];
            sqn1[tid] = g_SQN[base + 128 + tid];
        }
        asm volatile("cp.async.wait_group 0;" ::: "memory");
    }
    __syncthreads();

    // ---- invariant per-lane ldmatrix addressing ----
    uint32_t arsk = (uint32_t)((L >> 4) ^ (L & 7));
    uint32_t aB0  = sb + A_OFF + (uint32_t)(warpM * 32 + (L & 15)) * 512u;
    uint32_t aB1  = aB0 + 16 * 512;
    uint32_t brsk = (uint32_t)(((L >> 3) & 1) ^ (L & 7));
    uint32_t bB[4];
#pragma unroll
    for (int nb = 0; nb < 4; nb++)
        bB[nb] = sb + B_OFF +
                 (uint32_t)(warpN * 64 + nb * 16 + ((L >> 4) << 3) + (L & 7)) * 512u;

    const float L2E = 1.44269504f, LN2 = 0.69314718f;
    float wdiv = w_s * (1.0f / 15.0f);
    float total = 0.f;

    for (int t2 = 0; t2 < 2; t2++) {
        int rt = rtb + t2;
        float* sqn = t2 ? sqn1 : sqn0;

        // ---- mainloop: K=256 in 16 ksteps of k16 ----
        float acc[2][8][4];
#pragma unroll
        for (int f = 0; f < 2; f++)
#pragma unroll
            for (int j = 0; j < 8; j++)
#pragma unroll
                for (int u = 0; u < 4; u++) acc[f][j][u] = 0.f;

#pragma unroll 4
        for (int ks = 0; ks < 16; ks++) {
            uint32_t ku = (uint32_t)(ks * 2);
            uint32_t xa = ((ku ^ arsk) << 4);
            uint32_t xb = ((ku ^ brsk) << 4);
            uint32_t a0[4], a1[4];
            ldm_x4(a0, aB0 + xa);
            ldm_x4(a1, aB1 + xa);
#pragma unroll
            for (int nb = 0; nb < 4; nb++) {
                uint32_t bf[4];
                ldm_x4(bf, bB[nb] + xb);
                mma16816(acc[0][2 * nb],     a0, bf[0], bf[1]);
                mma16816(acc[0][2 * nb + 1], a0, bf[2], bf[3]);
                mma16816(acc[1][2 * nb],     a1, bf[0], bf[1]);
                mma16816(acc[1][2 * nb + 1], a1, bf[2], bf[3]);
            }
        }
        __syncthreads();   // all warps done reading A smem

        // prefetch next tile's A under the epilogue
        if (t2 == 0) {
            const char* Ag = (const char*)(g_Ebf +
                ((size_t)(batch * 4096 + (rtb + 1) * 128)) * DD);
#pragma unroll
            for (int it = 0; it < 8; it++) {
                int u = it * 512 + tid;
                cp_async16(sb + A_OFF + SWZ(u >> 5, u & 31), Ag + (size_t)u * 16);
            }
            asm volatile("cp.async.commit_group;" ::: "memory");
        }

        // ---- epilogue: in-place xv; direct diagonal SELF write; per-warp partial LSE ----
#pragma unroll
        for (int f = 0; f < 2; f++) {
            int dk = rt * 8 + warpM * 2 + f;
#pragma unroll
            for (int rh = 0; rh < 2; rh++) {
                int row = warpM * 32 + f * 16 + rh * 8 + (L >> 2);
                float sq = sqn[row];
                float m = -1e30f;
#pragma unroll
                for (int j = 0; j < 8; j++) {
#pragma unroll
                    for (int cq = 0; cq < 2; cq++) {
                        float v = acc[f][j][rh * 2 + cq];
                        int col = warpN * 64 + (j >> 1) * 16 + (j & 1) * 8 + (L & 3) * 2 + cq;
                        bool dg = (col == dk);
                        float xv = dg ? fmaf(wdiv, fmaf(16.f, v, -sq), b_s)
                                      : fmaf(w_s, v, b_s);
                        if (dg) SELF[row] = xv;          // unique lane owns the diagonal
                        acc[f][j][rh * 2 + cq] = xv;     // in-place for the sum pass
                        m = fmaxf(m, xv);
                    }
                }
                m = fmaxf(m, __shfl_xor_sync(0xFFFFFFFFu, m, 1));
                m = fmaxf(m, __shfl_xor_sync(0xFFFFFFFFu, m, 2));
                float s = 0.f;
#pragma unroll
                for (int j = 0; j < 8; j++) {
#pragma unroll
                    for (int cq = 0; cq < 2; cq++)
                        s += ex2f((acc[f][j][rh * 2 + cq] - m) * L2E);
                }
                s += __shfl_xor_sync(0xFFFFFFFFu, s, 1);
                s += __shfl_xor_sync(0xFFFFFFFFu, s, 2);
                if ((L & 3) == 0) msb[row * 4 + warpN] = make_float2(m, s);
            }
        }
        __syncthreads();

        // ---- merge 4 warpN partials per row, reduce ----
        if (tid < 128) {
            float2 p0 = msb[tid * 4 + 0], p1 = msb[tid * 4 + 1];
            float2 p2 = msb[tid * 4 + 2], p3 = msb[tid * 4 + 3];
            float m = fmaxf(fmaxf(p0.x, p1.x), fmaxf(p2.x, p3.x));
            float s = p0.y * ex2f((p0.x - m) * L2E) + p1.y * ex2f((p1.x - m) * L2E)
                    + p2.y * ex2f((p2.x - m) * L2E) + p3.y * ex2f((p3.x - m) * L2E);
            float contrib = m + lg2f(s) * LN2 - SELF[tid];
            contrib += __shfl_xor_sync(0xFFFFFFFFu, contrib, 16);
            contrib += __shfl_xor_sync(0xFFFFFFFFu, contrib, 8);
            contrib += __shfl_xor_sync(0xFFFFFFFFu, contrib, 4);
            contrib += __shfl_xor_sync(0xFFFFFFFFu, contrib, 2);
            contrib += __shfl_xor_sync(0xFFFFFFFFu, contrib, 1);
            if (L == 0) red[wid] = contrib;
        }
        __syncthreads();
        if (tid == 0) total += red[0] + red[1] + red[2] + red[3];
        if (t2 == 0) { asm volatile("cp.async.wait_group 0;" ::: "memory"); }
        __syncthreads();
    }

    if (tid == 0) atomicAdd(out, total);
}

// ============================ launch ============================
extern "C" void kernel_launch(void* const* d_in, const int* in_sizes, int n_in,
                              void* d_out, int out_size) {
    const float* E  = (const float*)d_in[0];
    const float* wp = (const float*)d_in[1];
    const float* bp = (const float*)d_in[2];
    float* out = (float*)d_out;

    centroid_kernel<<<BB * NN / 4, 256>>>(E, out);

    cudaFuncSetAttribute(loss_kernel, cudaFuncAttributeMaxDynamicSharedMemorySize, SMEM_TOTAL);
    loss_kernel<<<128, 512, SMEM_TOTAL>>>(wp, bp, out);
}